// round 13
// baseline (speedup 1.0000x reference)
#include <cuda_runtime.h>
#include <cuda_fp16.h>
#include <mma.h>
#include <cstdint>

using namespace nvcuda;

#define B_ 4
#define S_ 2048
#define H_ 1024
#define E_ 8
#define K_ 512
#define F_ 4096

// GEMM tiling (half inputs, fp32 accum), 256 threads, 8 warps 4(M)x2(N).
// ffn1: BM=128, BN=128 (warp 32x64). ffn2: BM=128, BN=64 (warp 32x32).
#define BM 128
#define BK 64
#define LDA_H 72     // halves; 144B row stride (conflict-free)
#define NSTAGE 3
#define LDB1 136     // BN=128 B stride
#define LDB2 72      // BN=64  B stride
#define LDC1 132
#define LDC2 68
#define SMEM1 (NSTAGE * (BM * LDA_H + BK * LDB1) * 2)   // 107520
#define SMEM2 (NSTAGE * (BM * LDA_H + BK * LDB2) * 2)   // 82944

// ---------------- scratch (device globals: allocation-guard-safe) ----------
__device__ float  g_scores[B_ * E_ * S_];
__device__ int    g_idx[B_ * E_ * K_];
__device__ float  g_gate[B_ * E_ * K_];
__device__ __half g_xgh[(size_t)B_ * E_ * K_ * H_];   // gathered tokens (half)
__device__ __half g_h1h[(size_t)B_ * E_ * K_ * F_];   // hidden (half), 134 MB
__device__ __half g_w1h[(size_t)E_ * H_ * F_];        // W1 as half, [E][H][F]
__device__ __half g_w2h[(size_t)E_ * F_ * H_];        // W2 as half, [E][F][H]

// ---------------- cp.async helpers -----------------------------------------
__device__ __forceinline__ uint32_t smem_u32(const void* p) {
    return (uint32_t)__cvta_generic_to_shared(p);
}
#define CP_ASYNC16(dst_u32, src_ptr) \
    asm volatile("cp.async.cg.shared.global [%0], [%1], 16;\n" :: "r"(dst_u32), "l"(src_ptr))
#define CP_COMMIT() asm volatile("cp.async.commit_group;\n" ::)
#define CP_WAIT1()  asm volatile("cp.async.wait_group 1;\n" ::)

// ---------------- kernel 1: gating + softmax -------------------------------
__global__ __launch_bounds__(256) void gate_kernel(const float* __restrict__ x,
                                                   const float* __restrict__ Wg) {
    int gwarp = (blockIdx.x * blockDim.x + threadIdx.x) >> 5;
    int lane = threadIdx.x & 31;
    int b = gwarp / S_, s = gwarp % S_;
    const float* xr = x + ((size_t)b * S_ + s) * H_;

    float acc[E_];
#pragma unroll
    for (int e = 0; e < E_; e++) acc[e] = 0.f;
    for (int h = lane; h < H_; h += 32) {
        float xv = xr[h];
#pragma unroll
        for (int e = 0; e < E_; e++) acc[e] += xv * Wg[e * H_ + h];
    }
#pragma unroll
    for (int e = 0; e < E_; e++) {
#pragma unroll
        for (int o = 16; o > 0; o >>= 1)
            acc[e] += __shfl_xor_sync(0xffffffffu, acc[e], o);
    }
    float mx = acc[0];
#pragma unroll
    for (int e = 1; e < E_; e++) mx = fmaxf(mx, acc[e]);
    float den = 0.f;
#pragma unroll
    for (int e = 0; e < E_; e++) den += expf(acc[e] - mx);
    if (lane < E_) {
        g_scores[((size_t)b * E_ + lane) * S_ + s] = expf(acc[lane] - mx) / den;
    }
}

// ---------------- kernel 2: top-K via 4-pass radix select ------------------
__global__ __launch_bounds__(256) void topk_kernel() {
    __shared__ unsigned int hist[256];
    __shared__ unsigned int s_sel, s_need, s_cnt, s_eq;
    int be = blockIdx.x;
    int tid = threadIdx.x;
    const unsigned int* sp = (const unsigned int*)(g_scores + (size_t)be * S_);

    unsigned int bits[8];
    int idxs[8];
#pragma unroll
    for (int j = 0; j < 8; j++) {
        int i = tid + j * 256;
        bits[j] = sp[i];
        idxs[j] = i;
    }
    if (tid == 0) { s_need = K_; s_cnt = 0; s_eq = 0; }

    unsigned int pref = 0, mask = 0;
#pragma unroll
    for (int p = 0; p < 4; p++) {
        int shift = 24 - 8 * p;
        hist[tid] = 0;
        __syncthreads();
#pragma unroll
        for (int j = 0; j < 8; j++) {
            if ((bits[j] & mask) == pref)
                atomicAdd(&hist[(bits[j] >> shift) & 255], 1u);
        }
        __syncthreads();
        if (tid < 32) {
            unsigned int mine[8];
            unsigned int partial = 0;
#pragma unroll
            for (int j = 0; j < 8; j++) {
                mine[j] = hist[255 - (tid * 8 + j)];
                partial += mine[j];
            }
            unsigned int inc = partial;
#pragma unroll
            for (int o = 1; o < 32; o <<= 1) {
                unsigned int v = __shfl_up_sync(0xffffffffu, inc, o);
                if (tid >= o) inc += v;
            }
            unsigned int exc = inc - partial;
            unsigned int need = s_need;
            bool has = (exc < need) && (need <= inc);
            unsigned int bal = __ballot_sync(0xffffffffu, has);
            int src = __ffs(bal) - 1;
            if (tid == src) {
                unsigned int acc = exc;
#pragma unroll
                for (int j = 0; j < 8; j++) {
                    if (acc + mine[j] >= need) {
                        s_sel = 255 - (unsigned int)(tid * 8 + j);
                        s_need = need - acc;
                        break;
                    }
                    acc += mine[j];
                }
            }
        }
        __syncthreads();
        pref |= (s_sel << shift);
        mask |= (0xFFu << shift);
        __syncthreads();
    }

    unsigned int T = pref;
    unsigned int needF = s_need;
#pragma unroll
    for (int j = 0; j < 8; j++) {
        unsigned int bv = bits[j];
        if (bv > T) {
            unsigned int pos = atomicAdd(&s_cnt, 1u);
            g_idx[(size_t)be * K_ + pos]  = idxs[j];
            g_gate[(size_t)be * K_ + pos] = __uint_as_float(bv);
        } else if (bv == T) {
            unsigned int t = atomicAdd(&s_eq, 1u);
            if (t < needF) {
                unsigned int pos = atomicAdd(&s_cnt, 1u);
                g_idx[(size_t)be * K_ + pos]  = idxs[j];
                g_gate[(size_t)be * K_ + pos] = __uint_as_float(bv);
            }
        }
    }
}

// ---------------- kernel 3: gather + zero(out) + weight convert ------------
// bids [0, GATHER_BLOCKS): gather chosen tokens -> half, zero `out` slice.
// bids [GATHER_BLOCKS, ...): fp32 -> fp16 weight convert (both W1, W2).
// All streaming / DRAM-bound work; safe to share one grid.
#define WELEMS ((size_t)E_ * H_ * F_)
#define GATHER_BLOCKS ((B_ * E_ * K_) / 8)             // 2048
#define CONV_BLOCKS ((int)((2 * WELEMS) / 2048))       // 32768

__global__ __launch_bounds__(256) void gatherconv_kernel(const float* __restrict__ x,
                                                         float* __restrict__ out,
                                                         const float* __restrict__ w1,
                                                         const float* __restrict__ w2,
                                                         __half* __restrict__ d1,
                                                         __half* __restrict__ d2) {
    if (blockIdx.x < GATHER_BLOCKS) {
        // zero 16 floats of out per thread (2048*256*16 = B*S*H)
        float4 z = make_float4(0.f, 0.f, 0.f, 0.f);
        float4* o4 = (float4*)out + (size_t)blockIdx.x * 1024 + threadIdx.x * 4;
        o4[0] = z; o4[1] = z; o4[2] = z; o4[3] = z;

        int row = blockIdx.x * 8 + (threadIdx.x >> 5);   // one warp per row
        int lane = threadIdx.x & 31;
        int be = row / K_;
        int b = be / E_;
        int token = g_idx[row];
        const float4* src = (const float4*)(x + ((size_t)b * S_ + token) * H_);
        __half2* dst = (__half2*)(g_xgh + (size_t)row * H_);
#pragma unroll
        for (int i = 0; i < 8; i++) {
            int idx = lane + i * 32;
            float4 v = src[idx];
            dst[idx * 2 + 0] = __floats2half2_rn(v.x, v.y);
            dst[idx * 2 + 1] = __floats2half2_rn(v.z, v.w);
        }
        return;
    }
    size_t i = ((size_t)(blockIdx.x - GATHER_BLOCKS) * 256 + threadIdx.x) * 8;
    const float* src = w1;
    __half* dst = d1;
    if (i >= WELEMS) { i -= WELEMS; src = w2; dst = d2; }
    float4 v0 = *(const float4*)(src + i);
    float4 v1 = *(const float4*)(src + i + 4);
    __half2 h[4];
    h[0] = __floats2half2_rn(v0.x, v0.y);
    h[1] = __floats2half2_rn(v0.z, v0.w);
    h[2] = __floats2half2_rn(v1.x, v1.y);
    h[3] = __floats2half2_rn(v1.z, v1.w);
    *(uint4*)(dst + i) = *(uint4*)h;
}

// GELU tanh approximation (JAX default approximate=True)
__device__ __forceinline__ float gelu_tanh(float v) {
    float t = 0.7978845608028654f * (v + 0.044715f * v * v * v);
    return 0.5f * v * (1.f + tanhf(t));
}

// ---------------- templated GEMM mainloop (half WMMA, fp32 accum) ----------
// C[128 x BNT] = A[128 x iters*64] @ B[iters*64 x N](row-major slice at n0).
// 3-stage cp.async ring, one syncthreads per iter, hoisted addressing.
template <int BNT, int LDBT, int NF>
__device__ __forceinline__ void gemm_half_t(
    const __half* __restrict__ A, size_t lda,
    const __half* __restrict__ Bg, size_t ldb,
    int n0, int iters, __half* sbase,
    wmma::fragment<wmma::accumulator, 16, 16, 16, float> (&acc)[2][NF],
    int tid) {
    constexpr int BCH = BNT / 32;                      // B 16B-chunks per thread
    constexpr int STG_H = BM * LDA_H + BK * LDBT;
    constexpr int STG_B = STG_H * 2;
    constexpr int BROW_CH = BNT / 8;                   // chunks per B row
    const int warp = tid >> 5;
    const int wm = warp & 3;
    const int wn = warp >> 2;

    uint32_t sAoff[4], sBoff[BCH];
    const __half* Ap[4];
    const __half* Bp[BCH];
    const uint32_t sb = smem_u32(sbase);
#pragma unroll
    for (int r = 0; r < 4; r++) {
        int g = tid + r * 256;
        int arow = g >> 3, ac = (g & 7) * 8;
        sAoff[r] = (uint32_t)(arow * LDA_H + ac) * 2;
        Ap[r] = A + (size_t)arow * lda + ac;
    }
#pragma unroll
    for (int r = 0; r < BCH; r++) {
        int g = tid + r * 256;
        int brow = g / BROW_CH, bc = (g % BROW_CH) * 8;
        sBoff[r] = (uint32_t)(BM * LDA_H + brow * LDBT + bc) * 2;
        Bp[r] = Bg + (size_t)brow * ldb + n0 + bc;
    }
    const size_t bstep = (size_t)BK * ldb;

    auto issue = [&](int j) {
        uint32_t stg = sb + (uint32_t)((j % NSTAGE) * STG_B);
        int k0 = j * BK;
        size_t bk = (size_t)j * bstep;
#pragma unroll
        for (int r = 0; r < 4; r++)
            CP_ASYNC16(stg + sAoff[r], Ap[r] + k0);
#pragma unroll
        for (int r = 0; r < BCH; r++)
            CP_ASYNC16(stg + sBoff[r], Bp[r] + bk);
    };

    issue(0); CP_COMMIT();
    issue(1); CP_COMMIT();
    for (int j = 0; j < iters; j++) {
        CP_WAIT1();
        __syncthreads();
        if (j + 2 < iters) issue(j + 2);
        CP_COMMIT();
        __half* st = sbase + (j % NSTAGE) * STG_H;
        __half* stB = st + BM * LDA_H;
        const __half* aw = st + (wm * 32) * LDA_H;
        const __half* bw = stB + wn * (NF * 16);
#pragma unroll
        for (int kk = 0; kk < BK; kk += 16) {
            wmma::fragment<wmma::matrix_a, 16, 16, 16, __half, wmma::row_major> af[2];
            wmma::fragment<wmma::matrix_b, 16, 16, 16, __half, wmma::row_major> bf[NF];
#pragma unroll
            for (int i = 0; i < 2; i++)
                wmma::load_matrix_sync(af[i], aw + i * 16 * LDA_H + kk, LDA_H);
#pragma unroll
            for (int jj = 0; jj < NF; jj++)
                wmma::load_matrix_sync(bf[jj], bw + kk * LDBT + jj * 16, LDBT);
#pragma unroll
            for (int i = 0; i < 2; i++)
#pragma unroll
                for (int jj = 0; jj < NF; jj++)
                    wmma::mma_sync(acc[i][jj], af[i], bf[jj], acc[i][jj]);
        }
    }
    __syncthreads();   // all reads done before smem reuse as C
}

// ---------------- kernel 4: FFN1 = gelu(Xg @ W1 + b1) -> half --------------
__global__ __launch_bounds__(256, 2) void ffn1_kernel(const float* __restrict__ b1) {
    extern __shared__ __align__(16) __half smem_h[];
    const int tid = threadIdx.x;
    const int e = blockIdx.z, b = blockIdx.y >> 2, mt = blockIdx.y & 3;
    const int n0 = blockIdx.x * 128, m0 = mt * BM;
    const int be = b * E_ + e;
    const int warp = tid >> 5, wm = warp & 3, wn = warp >> 2;

    const __half* A  = g_xgh + ((size_t)be * K_ + m0) * H_;
    const __half* Bg = g_w1h + (size_t)e * H_ * F_;

    wmma::fragment<wmma::accumulator, 16, 16, 16, float> acc[2][4];
#pragma unroll
    for (int i = 0; i < 2; i++)
#pragma unroll
        for (int j = 0; j < 4; j++) wmma::fill_fragment(acc[i][j], 0.f);

    gemm_half_t<128, LDB1, 4>(A, H_, Bg, F_, n0, H_ / BK, smem_h, acc, tid);

    float* sC = (float*)smem_h;
#pragma unroll
    for (int i = 0; i < 2; i++)
#pragma unroll
        for (int j = 0; j < 4; j++)
            wmma::store_matrix_sync(sC + (wm * 32 + i * 16) * LDC1 + wn * 64 + j * 16,
                                    acc[i][j], LDC1, wmma::mem_row_major);
    __syncthreads();

    const float* b1p = b1 + (size_t)e * F_ + n0;
    __half* h1p = g_h1h + ((size_t)be * K_ + m0) * F_ + n0;
#pragma unroll
    for (int r = 0; r < 16; r++) {
        int c = tid + r * 256;
        int row = c >> 5;
        int col = (c & 31) * 4;
        float4 v = *(const float4*)(sC + row * LDC1 + col);
        float4 bb = *(const float4*)(b1p + col);
        __half2 h0 = __floats2half2_rn(gelu_tanh(v.x + bb.x), gelu_tanh(v.y + bb.y));
        __half2 h1 = __floats2half2_rn(gelu_tanh(v.z + bb.z), gelu_tanh(v.w + bb.w));
        __half2* dp = (__half2*)(h1p + (size_t)row * F_ + col);
        dp[0] = h0;
        dp[1] = h1;
    }
}

// ---------------- kernel 5: FFN2 (BN=64) + bias + gate + scatter-add -------
// grid (H/64=16, 16, 8) = 2048 CTAs -> 6.9 waves (tail ~1%).
__global__ __launch_bounds__(256, 2) void ffn2_kernel(const float* __restrict__ b2,
                                                      float* __restrict__ out) {
    extern __shared__ __align__(16) __half smem_h[];
    const int tid = threadIdx.x;
    const int e = blockIdx.z, b = blockIdx.y >> 2, mt = blockIdx.y & 3;
    const int n0 = blockIdx.x * 64, m0 = mt * BM;
    const int be = b * E_ + e;
    const int warp = tid >> 5, wm = warp & 3, wn = warp >> 2;

    const __half* A  = g_h1h + ((size_t)be * K_ + m0) * F_;
    const __half* Bg = g_w2h + (size_t)e * F_ * H_;

    wmma::fragment<wmma::accumulator, 16, 16, 16, float> acc[2][2];
#pragma unroll
    for (int i = 0; i < 2; i++)
#pragma unroll
        for (int j = 0; j < 2; j++) wmma::fill_fragment(acc[i][j], 0.f);

    gemm_half_t<64, LDB2, 2>(A, F_, Bg, H_, n0, F_ / BK, smem_h, acc, tid);

    float* sC = (float*)smem_h;
#pragma unroll
    for (int i = 0; i < 2; i++)
#pragma unroll
        for (int j = 0; j < 2; j++)
            wmma::store_matrix_sync(sC + (wm * 32 + i * 16) * LDC2 + wn * 32 + j * 16,
                                    acc[i][j], LDC2, wmma::mem_row_major);
    __syncthreads();

    const int*   idxp  = g_idx  + (size_t)be * K_ + m0;
    const float* gatep = g_gate + (size_t)be * K_ + m0;
    const float* b2p   = b2 + (size_t)e * H_ + n0;
#pragma unroll
    for (int r = 0; r < 8; r++) {
        int c = tid + r * 256;
        int row = c >> 4;
        int col = (c & 15) * 4;
        float4 v = *(const float4*)(sC + row * LDC2 + col);
        float4 bb = *(const float4*)(b2p + col);
        float gsc = gatep[row];
        int token = idxp[row];
        float* op = out + ((size_t)b * S_ + token) * H_ + n0 + col;
        atomicAdd(op + 0, (v.x + bb.x) * gsc);
        atomicAdd(op + 1, (v.y + bb.y) * gsc);
        atomicAdd(op + 2, (v.z + bb.z) * gsc);
        atomicAdd(op + 3, (v.w + bb.w) * gsc);
    }
}

// ---------------- launch ----------------------------------------------------
extern "C" void kernel_launch(void* const* d_in, const int* in_sizes, int n_in,
                              void* d_out, int out_size) {
    const float* x  = (const float*)d_in[0];
    const float* Wg = (const float*)d_in[1];
    const float* W1 = (const float*)d_in[2];
    const float* b1 = (const float*)d_in[3];
    const float* W2 = (const float*)d_in[4];
    const float* b2 = (const float*)d_in[5];
    float* out = (float*)d_out;

    cudaFuncSetAttribute(ffn1_kernel, cudaFuncAttributeMaxDynamicSharedMemorySize, SMEM1);
    cudaFuncSetAttribute(ffn2_kernel, cudaFuncAttributeMaxDynamicSharedMemorySize, SMEM2);

    __half* w1h; cudaGetSymbolAddress((void**)&w1h, g_w1h);
    __half* w2h; cudaGetSymbolAddress((void**)&w2h, g_w2h);

    // 3 kernels before ffn1 -> ffn1 lands in the profiler's capture slot.
    gate_kernel<<<(B_ * S_) / 8, 256>>>(x, Wg);
    topk_kernel<<<B_ * E_, 256>>>();
    gatherconv_kernel<<<GATHER_BLOCKS + CONV_BLOCKS, 256>>>(x, out, W1, W2, w1h, w2h);
    ffn1_kernel<<<dim3(F_ / 128, (B_ * K_) / BM, E_), 256, SMEM1>>>(b1);
    ffn2_kernel<<<dim3(H_ / 64, (B_ * K_) / BM, E_), 256, SMEM2>>>(b2, out);
}

// round 14
// speedup vs baseline: 1.0718x; 1.0718x over previous
#include <cuda_runtime.h>
#include <cuda_fp16.h>
#include <mma.h>
#include <cstdint>

using namespace nvcuda;

#define B_ 4
#define S_ 2048
#define H_ 1024
#define E_ 8
#define K_ 512
#define F_ 4096

// GEMM tiling (half inputs, fp32 accum): block 128x128x64, 256 threads,
// 8 warps as 4(M) x 2(N), warp tile 32x64.
#define BM 128
#define BN 128
#define BK 64
#define LDA_H 72    // halves; 144B row stride (conflict-free)
#define LDB_H 136   // halves; 272B row stride (conflict-free)
#define LDC 132
#define NSTAGE 3
#define STAGE_HALVES (BM * LDA_H + BK * LDB_H)     // 17920
#define STAGE_BYTES (STAGE_HALVES * 2)             // 35840
#define SMEM_BYTES (NSTAGE * STAGE_BYTES)          // 107520

// ---------------- scratch (device globals: allocation-guard-safe) ----------
__device__ float  g_scores[B_ * E_ * S_];
__device__ int    g_idx[B_ * E_ * K_];
__device__ float  g_gate[B_ * E_ * K_];
__device__ __half g_xgh[(size_t)B_ * E_ * K_ * H_];   // gathered tokens (half)
__device__ __half g_h1h[(size_t)B_ * E_ * K_ * F_];   // hidden (half), 134 MB
__device__ __half g_w1h[(size_t)E_ * H_ * F_];        // W1 as half, [E][H][F]
__device__ __half g_w2h[(size_t)E_ * F_ * H_];        // W2 as half, [E][F][H]

// ---------------- cp.async helpers -----------------------------------------
__device__ __forceinline__ uint32_t smem_u32(const void* p) {
    return (uint32_t)__cvta_generic_to_shared(p);
}
#define CP_ASYNC16(dst_u32, src_ptr) \
    asm volatile("cp.async.cg.shared.global [%0], [%1], 16;\n" :: "r"(dst_u32), "l"(src_ptr))
#define CP_COMMIT() asm volatile("cp.async.commit_group;\n" ::)
#define CP_WAIT1()  asm volatile("cp.async.wait_group 1;\n" ::)

// 8-element fp32 -> fp16 convert (coalesced 32B load, 16B store)
__device__ __forceinline__ void conv8(const float* __restrict__ src,
                                      __half* __restrict__ dst, size_t i) {
    float4 v0 = *(const float4*)(src + i);
    float4 v1 = *(const float4*)(src + i + 4);
    __half2 h[4];
    h[0] = __floats2half2_rn(v0.x, v0.y);
    h[1] = __floats2half2_rn(v0.z, v0.w);
    h[2] = __floats2half2_rn(v1.x, v1.y);
    h[3] = __floats2half2_rn(v1.z, v1.w);
    *(uint4*)(dst + i) = *(uint4*)h;
}

// ---------------- kernel 1: gating + softmax -------------------------------
__global__ __launch_bounds__(256) void gate_kernel(const float* __restrict__ x,
                                                   const float* __restrict__ Wg) {
    int gwarp = (blockIdx.x * blockDim.x + threadIdx.x) >> 5;
    int lane = threadIdx.x & 31;
    int b = gwarp / S_, s = gwarp % S_;
    const float* xr = x + ((size_t)b * S_ + s) * H_;

    float acc[E_];
#pragma unroll
    for (int e = 0; e < E_; e++) acc[e] = 0.f;
    for (int h = lane; h < H_; h += 32) {
        float xv = xr[h];
#pragma unroll
        for (int e = 0; e < E_; e++) acc[e] += xv * Wg[e * H_ + h];
    }
#pragma unroll
    for (int e = 0; e < E_; e++) {
#pragma unroll
        for (int o = 16; o > 0; o >>= 1)
            acc[e] += __shfl_xor_sync(0xffffffffu, acc[e], o);
    }
    float mx = acc[0];
#pragma unroll
    for (int e = 1; e < E_; e++) mx = fmaxf(mx, acc[e]);
    float den = 0.f;
#pragma unroll
    for (int e = 0; e < E_; e++) den += expf(acc[e] - mx);
    if (lane < E_) {
        g_scores[((size_t)b * E_ + lane) * S_ + s] = expf(acc[lane] - mx) / den;
    }
}

// ---------------- kernel 2: top-K via 4-pass radix select ------------------
__global__ __launch_bounds__(256) void topk_kernel() {
    __shared__ unsigned int hist[256];
    __shared__ unsigned int s_sel, s_need, s_cnt, s_eq;
    int be = blockIdx.x;
    int tid = threadIdx.x;
    const unsigned int* sp = (const unsigned int*)(g_scores + (size_t)be * S_);

    unsigned int bits[8];
    int idxs[8];
#pragma unroll
    for (int j = 0; j < 8; j++) {
        int i = tid + j * 256;
        bits[j] = sp[i];
        idxs[j] = i;
    }
    if (tid == 0) { s_need = K_; s_cnt = 0; s_eq = 0; }

    unsigned int pref = 0, mask = 0;
#pragma unroll
    for (int p = 0; p < 4; p++) {
        int shift = 24 - 8 * p;
        hist[tid] = 0;
        __syncthreads();
#pragma unroll
        for (int j = 0; j < 8; j++) {
            if ((bits[j] & mask) == pref)
                atomicAdd(&hist[(bits[j] >> shift) & 255], 1u);
        }
        __syncthreads();
        if (tid < 32) {
            unsigned int mine[8];
            unsigned int partial = 0;
#pragma unroll
            for (int j = 0; j < 8; j++) {
                mine[j] = hist[255 - (tid * 8 + j)];
                partial += mine[j];
            }
            unsigned int inc = partial;
#pragma unroll
            for (int o = 1; o < 32; o <<= 1) {
                unsigned int v = __shfl_up_sync(0xffffffffu, inc, o);
                if (tid >= o) inc += v;
            }
            unsigned int exc = inc - partial;
            unsigned int need = s_need;
            bool has = (exc < need) && (need <= inc);
            unsigned int bal = __ballot_sync(0xffffffffu, has);
            int src = __ffs(bal) - 1;
            if (tid == src) {
                unsigned int acc = exc;
#pragma unroll
                for (int j = 0; j < 8; j++) {
                    if (acc + mine[j] >= need) {
                        s_sel = 255 - (unsigned int)(tid * 8 + j);
                        s_need = need - acc;
                        break;
                    }
                    acc += mine[j];
                }
            }
        }
        __syncthreads();
        pref |= (s_sel << shift);
        mask |= (0xFFu << shift);
        __syncthreads();
    }

    unsigned int T = pref;
    unsigned int needF = s_need;
#pragma unroll
    for (int j = 0; j < 8; j++) {
        unsigned int bv = bits[j];
        if (bv > T) {
            unsigned int pos = atomicAdd(&s_cnt, 1u);
            g_idx[(size_t)be * K_ + pos]  = idxs[j];
            g_gate[(size_t)be * K_ + pos] = __uint_as_float(bv);
        } else if (bv == T) {
            unsigned int t = atomicAdd(&s_eq, 1u);
            if (t < needF) {
                unsigned int pos = atomicAdd(&s_cnt, 1u);
                g_idx[(size_t)be * K_ + pos]  = idxs[j];
                g_gate[(size_t)be * K_ + pos] = __uint_as_float(bv);
            }
        }
    }
}

// ---------------- kernel 3: gather + zero(out) + convert W1 ----------------
// 2048 blocks. Per block: zero 16KB of out, gather 8 token rows, and convert
// a 16384-elem slice of W1 (all DRAM-streaming; co-scheduled fine).
#define W1ELEMS ((size_t)E_ * H_ * F_)
__global__ __launch_bounds__(256) void gather_kernel(const float* __restrict__ x,
                                                     float* __restrict__ out,
                                                     const float* __restrict__ w1,
                                                     __half* __restrict__ d1) {
    // zero out slice: 2048 blocks x 256 thr x 16 floats = B*S*H
    {
        float4 z = make_float4(0.f, 0.f, 0.f, 0.f);
        float4* o4 = (float4*)out + (size_t)blockIdx.x * 1024 + threadIdx.x * 4;
        o4[0] = z; o4[1] = z; o4[2] = z; o4[3] = z;
    }
    // gather: one warp per chosen-token row
    int row = blockIdx.x * 8 + (threadIdx.x >> 5);
    int lane = threadIdx.x & 31;
    int be = row / K_;
    int b = be / E_;
    int token = g_idx[row];
    const float4* src = (const float4*)(x + ((size_t)b * S_ + token) * H_);
    __half2* dst = (__half2*)(g_xgh + (size_t)row * H_);
#pragma unroll
    for (int i = 0; i < 8; i++) {
        int idx = lane + i * 32;
        float4 v = src[idx];
        dst[idx * 2 + 0] = __floats2half2_rn(v.x, v.y);
        dst[idx * 2 + 1] = __floats2half2_rn(v.z, v.w);
    }
    // convert W1 slice: 16384 elems per block (2048 blocks cover 33.5M)
    size_t base = (size_t)blockIdx.x * 16384 + threadIdx.x * 8;
#pragma unroll
    for (int it = 0; it < 8; it++)
        conv8(w1, d1, base + (size_t)it * 2048);
}

// GELU tanh approximation (JAX default approximate=True)
__device__ __forceinline__ float gelu_tanh(float v) {
    float t = 0.7978845608028654f * (v + 0.044715f * v * v * v);
    return 0.5f * v * (1.f + tanhf(t));
}

// ---------------- shared GEMM mainloop (half WMMA, fp32 accum) -------------
// 3-stage cp.async ring, one syncthreads per iteration, hoisted addressing.
struct AccTile {
    wmma::fragment<wmma::accumulator, 16, 16, 16, float> a[2][4];
};

__device__ __forceinline__ void gemm_half(const __half* __restrict__ A, size_t lda,
                                          const __half* __restrict__ Bg, size_t ldb,
                                          int n0, int iters, __half* sbase,
                                          AccTile& acc, int tid) {
    const int warp = tid >> 5;
    const int wm = warp & 3;
    const int wn = warp >> 2;

    uint32_t sAoff[4], sBoff[4];
    const __half* Ap[4];
    const __half* Bp[4];
    const uint32_t sb = smem_u32(sbase);
#pragma unroll
    for (int r = 0; r < 4; r++) {
        int g = tid + r * 256;
        int arow = g >> 3, ac = (g & 7) * 8;
        sAoff[r] = (uint32_t)(arow * LDA_H + ac) * 2;
        Ap[r] = A + (size_t)arow * lda + ac;
        int brow = g >> 4, bc = (g & 15) * 8;
        sBoff[r] = (uint32_t)(BM * LDA_H + brow * LDB_H + bc) * 2;
        Bp[r] = Bg + (size_t)brow * ldb + n0 + bc;
    }
    const size_t bstep = (size_t)BK * ldb;

    auto issue = [&](int j) {
        uint32_t stg = sb + (uint32_t)((j % NSTAGE) * STAGE_BYTES);
        int k0 = j * BK;
        size_t bk = (size_t)j * bstep;
#pragma unroll
        for (int r = 0; r < 4; r++)
            CP_ASYNC16(stg + sAoff[r], Ap[r] + k0);
#pragma unroll
        for (int r = 0; r < 4; r++)
            CP_ASYNC16(stg + sBoff[r], Bp[r] + bk);
    };

    issue(0); CP_COMMIT();
    issue(1); CP_COMMIT();
    for (int j = 0; j < iters; j++) {
        CP_WAIT1();
        __syncthreads();
        if (j + 2 < iters) issue(j + 2);
        CP_COMMIT();
        __half* st = sbase + (j % NSTAGE) * STAGE_HALVES;
        __half* stB = st + BM * LDA_H;
        const __half* aw = st + (wm * 32) * LDA_H;
        const __half* bw = stB + wn * 64;
#pragma unroll
        for (int kk = 0; kk < BK; kk += 16) {
            wmma::fragment<wmma::matrix_a, 16, 16, 16, __half, wmma::row_major> af[2];
            wmma::fragment<wmma::matrix_b, 16, 16, 16, __half, wmma::row_major> bf[4];
#pragma unroll
            for (int i = 0; i < 2; i++)
                wmma::load_matrix_sync(af[i], aw + i * 16 * LDA_H + kk, LDA_H);
#pragma unroll
            for (int jj = 0; jj < 4; jj++)
                wmma::load_matrix_sync(bf[jj], bw + kk * LDB_H + jj * 16, LDB_H);
#pragma unroll
            for (int i = 0; i < 2; i++)
#pragma unroll
                for (int jj = 0; jj < 4; jj++)
                    wmma::mma_sync(acc.a[i][jj], af[i], bf[jj], acc.a[i][jj]);
        }
    }
    __syncthreads();   // all reads done before smem reuse as C
}

__device__ __forceinline__ void store_acc_smem(float* sC, AccTile& acc, int tid) {
    const int warp = tid >> 5;
    const int wm = warp & 3;
    const int wn = warp >> 2;
#pragma unroll
    for (int i = 0; i < 2; i++)
#pragma unroll
        for (int j = 0; j < 4; j++)
            wmma::store_matrix_sync(sC + (wm * 32 + i * 16) * LDC + wn * 64 + j * 16,
                                    acc.a[i][j], LDC, wmma::mem_row_major);
}

// ---------------- kernel 4: FFN1 + trailing W2-convert slice ---------------
// After its GEMM+epilogue, each of the 4096 CTAs converts 8192 elems of W2
// (fp32 -> fp16). This hides the entire W2 conversion in ffn1's idle DRAM
// bandwidth (ffn1 measured at 5.6% DRAM); ffn2 launches only after this
// kernel completes, so ordering is guaranteed.
#define W2ELEMS ((size_t)E_ * F_ * H_)
__global__ __launch_bounds__(256, 2) void ffn1_kernel(const float* __restrict__ b1,
                                                      const float* __restrict__ w2,
                                                      __half* __restrict__ d2) {
    extern __shared__ __align__(16) __half smem_h[];
    const int tid = threadIdx.x;
    const int e = blockIdx.z, b = blockIdx.y >> 2, mt = blockIdx.y & 3;
    const int n0 = blockIdx.x * BN, m0 = mt * BM;
    const int be = b * E_ + e;

    const __half* A  = g_xgh + ((size_t)be * K_ + m0) * H_;
    const __half* Bg = g_w1h + (size_t)e * H_ * F_;

    AccTile acc;
#pragma unroll
    for (int i = 0; i < 2; i++)
#pragma unroll
        for (int j = 0; j < 4; j++) wmma::fill_fragment(acc.a[i][j], 0.f);

    gemm_half(A, H_, Bg, F_, n0, H_ / BK, smem_h, acc, tid);

    float* sC = (float*)smem_h;
    store_acc_smem(sC, acc, tid);
    __syncthreads();

    const float* b1p = b1 + (size_t)e * F_ + n0;
    __half* h1p = g_h1h + ((size_t)be * K_ + m0) * F_ + n0;
#pragma unroll
    for (int r = 0; r < 16; r++) {
        int c = tid + r * 256;
        int row = c >> 5;
        int col = (c & 31) * 4;
        float4 v = *(const float4*)(sC + row * LDC + col);
        float4 bb = *(const float4*)(b1p + col);
        __half2 h0 = __floats2half2_rn(gelu_tanh(v.x + bb.x), gelu_tanh(v.y + bb.y));
        __half2 h1 = __floats2half2_rn(gelu_tanh(v.z + bb.z), gelu_tanh(v.w + bb.w));
        __half2* dp = (__half2*)(h1p + (size_t)row * F_ + col);
        dp[0] = h0;
        dp[1] = h1;
    }

    // trailing W2-convert slice: bid in [0,4096), 8192 elems each
    int bid = (blockIdx.z * 16 + blockIdx.y) * 32 + blockIdx.x;
    size_t base = (size_t)bid * 8192 + tid * 8;
#pragma unroll
    for (int it = 0; it < 4; it++)
        conv8(w2, d2, base + (size_t)it * 2048);
}

// ---------------- kernel 5: FFN2 + bias + gate + scatter-add ---------------
__global__ __launch_bounds__(256, 2) void ffn2_kernel(const float* __restrict__ b2,
                                                      float* __restrict__ out) {
    extern __shared__ __align__(16) __half smem_h[];
    const int tid = threadIdx.x;
    const int e = blockIdx.z, b = blockIdx.y >> 2, mt = blockIdx.y & 3;
    const int n0 = blockIdx.x * BN, m0 = mt * BM;
    const int be = b * E_ + e;

    const __half* A  = g_h1h + ((size_t)be * K_ + m0) * F_;
    const __half* Bg = g_w2h + (size_t)e * F_ * H_;

    AccTile acc;
#pragma unroll
    for (int i = 0; i < 2; i++)
#pragma unroll
        for (int j = 0; j < 4; j++) wmma::fill_fragment(acc.a[i][j], 0.f);

    gemm_half(A, F_, Bg, H_, n0, F_ / BK, smem_h, acc, tid);

    float* sC = (float*)smem_h;
    store_acc_smem(sC, acc, tid);
    __syncthreads();

    const int*   idxp  = g_idx  + (size_t)be * K_ + m0;
    const float* gatep = g_gate + (size_t)be * K_ + m0;
    const float* b2p   = b2 + (size_t)e * H_ + n0;
#pragma unroll
    for (int r = 0; r < 16; r++) {
        int c = tid + r * 256;
        int row = c >> 5;
        int col = (c & 31) * 4;
        float4 v = *(const float4*)(sC + row * LDC + col);
        float4 bb = *(const float4*)(b2p + col);
        float gsc = gatep[row];
        int token = idxp[row];
        float* op = out + ((size_t)b * S_ + token) * H_ + n0 + col;
        atomicAdd(op + 0, (v.x + bb.x) * gsc);
        atomicAdd(op + 1, (v.y + bb.y) * gsc);
        atomicAdd(op + 2, (v.z + bb.z) * gsc);
        atomicAdd(op + 3, (v.w + bb.w) * gsc);
    }
}

// ---------------- launch ----------------------------------------------------
extern "C" void kernel_launch(void* const* d_in, const int* in_sizes, int n_in,
                              void* d_out, int out_size) {
    const float* x  = (const float*)d_in[0];
    const float* Wg = (const float*)d_in[1];
    const float* W1 = (const float*)d_in[2];
    const float* b1 = (const float*)d_in[3];
    const float* W2 = (const float*)d_in[4];
    const float* b2 = (const float*)d_in[5];
    float* out = (float*)d_out;

    cudaFuncSetAttribute(ffn1_kernel, cudaFuncAttributeMaxDynamicSharedMemorySize, SMEM_BYTES);
    cudaFuncSetAttribute(ffn2_kernel, cudaFuncAttributeMaxDynamicSharedMemorySize, SMEM_BYTES);

    __half* w1h; cudaGetSymbolAddress((void**)&w1h, g_w1h);
    __half* w2h; cudaGetSymbolAddress((void**)&w2h, g_w2h);

    gate_kernel<<<(B_ * S_) / 8, 256>>>(x, Wg);
    topk_kernel<<<B_ * E_, 256>>>();
    gather_kernel<<<(B_ * E_ * K_) / 8, 256>>>(x, out, W1, w1h);
    ffn1_kernel<<<dim3(F_ / BN, (B_ * K_) / BM, E_), 256, SMEM_BYTES>>>(b1, W2, w2h);
    ffn2_kernel<<<dim3(H_ / BN, (B_ * K_) / BM, E_), 256, SMEM_BYTES>>>(b2, out);
}